// round 5
// baseline (speedup 1.0000x reference)
#include <cuda_runtime.h>
#include <cuda_fp16.h>
#include <stdint.h>

// ---------------------------------------------------------------------------
// Sparse gather-MLP:
//   vals = inputs (B x 128)
//   for l in 0..7: pre[b,w] = sum_k vals[b, edge[l,w,k]] * W[l,w,k] + bias[l,w]
//                  vals = concat(vals, sigmoid(pre))
//   out = last 256 columns
//
// Design: per-block batch tile of R=60 rows kept entirely in shared memory,
// feature-major fp16 [feat][60 rows]. Gather index is uniform across the warp
// (depends only on (l,w,k)), lanes map to row-pairs -> conflict-free LDS.32
// of half2 (2 rows per lane). fp16 HFMA2 into 4 rotating accumulators
// (<=4 terms each), combined + biased + sigmoid in fp32. Per-(w,k) index and
// weight prepacked into {byte_offset, half2(w)} read via uniform LDG.128.
// Layer 7 written coalesced to transposed scratch [256][B], then transposed.
// ---------------------------------------------------------------------------

#define NLAYER 8
#define WIDTH  256
#define KK     16
#define NIN    128
#define BB     32768
#define RROWS  60
#define ROW_BYTES (RROWS * 2)                       // 120 bytes per feature row
#define TOTAL_FEAT (NIN + (NLAYER - 1) * WIDTH)     // 1920 stored features
#define SMEM_BYTES (TOTAL_FEAT * ROW_BYTES + 256)   // + pad for lane-31 overread
#define NPAIR (NLAYER * WIDTH * KK)

struct Pair { uint32_t off; uint32_t w2; };         // byte offset, half2 weight

__device__ Pair  g_pairs[NPAIR];                    // 256 KB prepacked table
__device__ float g_out_t[(size_t)WIDTH * BB];       // transposed output scratch

// --------------------------- prepack -------------------------------------
__global__ void prepack_kernel(const float* __restrict__ w,
                               const int* __restrict__ e) {
    int i = blockIdx.x * blockDim.x + threadIdx.x;
    if (i < NPAIR) {
        __half2 h = __float2half2_rn(w[i]);
        Pair p;
        p.off = (uint32_t)e[i] * (uint32_t)ROW_BYTES;
        p.w2  = *reinterpret_cast<uint32_t*>(&h);
        g_pairs[i] = p;
    }
}

__device__ __forceinline__ __half2 h2bits(uint32_t u) {
    return *reinterpret_cast<__half2*>(&u);
}

// --------------------------- one layer ------------------------------------
template <bool LAST>
__device__ __forceinline__ void do_layer(char* sm, int l, int warp, int lane,
                                         const float* __restrict__ biases,
                                         int row0, bool active) {
    const int width = NIN + l * WIDTH;
    const int w0    = warp * 32;                 // 8 warps x 32 units = 256
    const Pair*  pt = g_pairs + (size_t)(l * WIDTH + w0) * KK;
    const float* bl = biases + l * WIDTH + w0;
    const int    lb = lane * 4;                  // byte offset of this lane's row pair

    // prefetch unit 0's 16 pairs (8 x uint4, uniform address -> 1 sector each)
    const uint4* p = reinterpret_cast<const uint4*>(pt);
    uint4 q0 = __ldg(p + 0), q1 = __ldg(p + 1), q2 = __ldg(p + 2), q3 = __ldg(p + 3);
    uint4 q4 = __ldg(p + 4), q5 = __ldg(p + 5), q6 = __ldg(p + 6), q7 = __ldg(p + 7);

#pragma unroll 1
    for (int u = 0; u < 32; ++u) {
        uint4 n0, n1, n2, n3, n4, n5, n6, n7;
        if (u < 31) {   // software prefetch next unit's pairs (hide L2 latency)
            const uint4* pn = reinterpret_cast<const uint4*>(pt + (u + 1) * KK);
            n0 = __ldg(pn + 0); n1 = __ldg(pn + 1); n2 = __ldg(pn + 2); n3 = __ldg(pn + 3);
            n4 = __ldg(pn + 4); n5 = __ldg(pn + 5); n6 = __ldg(pn + 6); n7 = __ldg(pn + 7);
        } else {
            n0 = q0; n1 = q1; n2 = q2; n3 = q3; n4 = q4; n5 = q5; n6 = q6; n7 = q7;
        }

        __half2 a0 = __float2half2_rn(0.f), a1 = a0, a2 = a0, a3 = a0;
        // 16 gathers, round-robin over 4 fp16 accumulators (<=4 terms each)
        a0 = __hfma2(*(const __half2*)(sm + q0.x + lb), h2bits(q0.y), a0);
        a1 = __hfma2(*(const __half2*)(sm + q0.z + lb), h2bits(q0.w), a1);
        a2 = __hfma2(*(const __half2*)(sm + q1.x + lb), h2bits(q1.y), a2);
        a3 = __hfma2(*(const __half2*)(sm + q1.z + lb), h2bits(q1.w), a3);
        a0 = __hfma2(*(const __half2*)(sm + q2.x + lb), h2bits(q2.y), a0);
        a1 = __hfma2(*(const __half2*)(sm + q2.z + lb), h2bits(q2.w), a1);
        a2 = __hfma2(*(const __half2*)(sm + q3.x + lb), h2bits(q3.y), a2);
        a3 = __hfma2(*(const __half2*)(sm + q3.z + lb), h2bits(q3.w), a3);
        a0 = __hfma2(*(const __half2*)(sm + q4.x + lb), h2bits(q4.y), a0);
        a1 = __hfma2(*(const __half2*)(sm + q4.z + lb), h2bits(q4.w), a1);
        a2 = __hfma2(*(const __half2*)(sm + q5.x + lb), h2bits(q5.y), a2);
        a3 = __hfma2(*(const __half2*)(sm + q5.z + lb), h2bits(q5.w), a3);
        a0 = __hfma2(*(const __half2*)(sm + q6.x + lb), h2bits(q6.y), a0);
        a1 = __hfma2(*(const __half2*)(sm + q6.z + lb), h2bits(q6.w), a1);
        a2 = __hfma2(*(const __half2*)(sm + q7.x + lb), h2bits(q7.y), a2);
        a3 = __hfma2(*(const __half2*)(sm + q7.z + lb), h2bits(q7.w), a3);

        // combine in fp32, add bias, sigmoid
        float2 f0 = __half22float2(a0), f1 = __half22float2(a1);
        float2 f2 = __half22float2(a2), f3 = __half22float2(a3);
        float  b  = __ldg(bl + u);
        float  sx = ((f0.x + f1.x) + (f2.x + f3.x)) + b;   // row 2*lane
        float  sy = ((f0.y + f1.y) + (f2.y + f3.y)) + b;   // row 2*lane+1
        float  s0 = __fdividef(1.f, 1.f + __expf(-sx));
        float  s1 = __fdividef(1.f, 1.f + __expf(-sy));

        if (active) {
            if (!LAST) {
                *(__half2*)(sm + (width + w0 + u) * ROW_BYTES + lb) =
                    __floats2half2_rn(s0, s1);
            } else {
                int r = row0 + 2 * lane;
                if (r < BB) {   // B even, rows pair-aligned -> one guard suffices
                    *reinterpret_cast<float2*>(&g_out_t[(size_t)(w0 + u) * BB + r]) =
                        make_float2(s0, s1);
                }
            }
        }

        q0 = n0; q1 = n1; q2 = n2; q3 = n3; q4 = n4; q5 = n5; q6 = n6; q7 = n7;
    }
}

// --------------------------- main kernel -----------------------------------
__global__ void __launch_bounds__(256, 1)
ffn_main(const float* __restrict__ inp, const float* __restrict__ biases) {
    extern __shared__ char sm[];
    const int tid  = threadIdx.x;
    const int lane = tid & 31;
    const int warp = tid >> 5;
    const int row0 = blockIdx.x * RROWS;

    // stage input tile [60 rows x 128 feats] transposed into smem as fp16
    for (int idx = tid; idx < RROWS * NIN; idx += 256) {
        int r = idx >> 7;          // 0..59
        int c = idx & 127;         // coalesced gmem read over c
        float v = 0.f;
        int gr = row0 + r;
        if (gr < BB) v = inp[gr * NIN + c];
        *reinterpret_cast<__half*>(sm + c * ROW_BYTES + r * 2) = __float2half_rn(v);
    }
    __syncthreads();

    const bool active = lane < (RROWS / 2);   // 30 row-pairs per warp

#pragma unroll 1
    for (int l = 0; l < NLAYER - 1; ++l) {
        do_layer<false>(sm, l, warp, lane, biases, row0, active);
        __syncthreads();   // layer-l outputs visible before layer-(l+1) gathers
    }
    do_layer<true>(sm, NLAYER - 1, warp, lane, biases, row0, active);
}

// --------------------------- output transpose ------------------------------
__global__ void transpose_kernel(float* __restrict__ out) {
    __shared__ float t[32][33];
    int rb = blockIdx.x * 32;    // row tile
    int cb = blockIdx.y * 32;    // feature tile
    int x = threadIdx.x, y = threadIdx.y;   // 32 x 8
#pragma unroll
    for (int i = 0; i < 32; i += 8)
        t[y + i][x] = g_out_t[(size_t)(cb + y + i) * BB + rb + x];
    __syncthreads();
#pragma unroll
    for (int i = 0; i < 32; i += 8)
        out[(size_t)(rb + y + i) * WIDTH + cb + x] = t[x][y + i];
}

// --------------------------- launcher --------------------------------------
extern "C" void kernel_launch(void* const* d_in, const int* in_sizes, int n_in,
                              void* d_out, int out_size) {
    const float* inp     = (const float*)d_in[0];   // (32768, 128) f32
    const float* weights = (const float*)d_in[1];   // (8, 256, 16) f32
    const float* biases  = (const float*)d_in[2];   // (8, 256)     f32
    const int*   edge    = (const int*)  d_in[3];   // (8, 256, 16) i32
    float* out = (float*)d_out;                     // (32768, 256) f32

    cudaFuncSetAttribute(ffn_main, cudaFuncAttributeMaxDynamicSharedMemorySize,
                         SMEM_BYTES);

    prepack_kernel<<<(NPAIR + 255) / 256, 256>>>(weights, edge);
    ffn_main<<<(BB + RROWS - 1) / RROWS, 256, SMEM_BYTES>>>(inp, biases);
    transpose_kernel<<<dim3(BB / 32, WIDTH / 32), dim3(32, 8)>>>(out);
}

// round 6
// speedup vs baseline: 1.1827x; 1.1827x over previous
#include <cuda_runtime.h>
#include <cuda_fp16.h>
#include <stdint.h>

// ---------------------------------------------------------------------------
// Sparse gather-MLP (B=32768, 8 layers, W=256, K=16 random gathers/unit).
//
// Design: per-block batch tile of R=60 rows entirely in shared memory,
// feature-major fp16 [feat][60 rows]. Gather index is uniform across the warp
// -> conflict-free broadcast-indexed LDS.32 of half2 (2 rows per lane,
// lanes 0..29 active). fp16 HFMA2 into 4 rotating accumulators, combined +
// bias + sigmoid in fp32. Pair table {byte_off, half2(w)} prepacked in gmem,
// read via uniform LDG.128 with one-unit software prefetch.
//
// R5 changes vs R0: 512 threads (16 warps, 4/SMSP) for latency hiding with
// 16 units/warp; MUFU.TANH-based sigmoid on hidden layers (exp-based kept on
// the output layer for accuracy).
// ---------------------------------------------------------------------------

#define NLAYER 8
#define WIDTH  256
#define KK     16
#define NIN    128
#define BB     32768
#define RROWS  60
#define ROW_BYTES (RROWS * 2)                       // 120 bytes per feature row
#define TOTAL_FEAT (NIN + (NLAYER - 1) * WIDTH)     // 1920 stored features
#define SMEM_BYTES (TOTAL_FEAT * ROW_BYTES + 256)   // + pad for lane 30/31 overread
#define NPAIR (NLAYER * WIDTH * KK)
#define NTHREADS 512
#define UNITS_PER_WARP (WIDTH / (NTHREADS / 32))    // 16

struct Pair { uint32_t off; uint32_t w2; };         // byte offset, half2 weight

__device__ Pair  g_pairs[NPAIR];                    // 256 KB prepacked table
__device__ float g_out_t[(size_t)WIDTH * BB];       // transposed output scratch

// --------------------------- prepack -------------------------------------
__global__ void prepack_kernel(const float* __restrict__ w,
                               const int* __restrict__ e) {
    int i = blockIdx.x * blockDim.x + threadIdx.x;
    if (i < NPAIR) {
        __half2 h = __float2half2_rn(w[i]);
        Pair p;
        p.off = (uint32_t)e[i] * (uint32_t)ROW_BYTES;
        p.w2  = *reinterpret_cast<uint32_t*>(&h);
        g_pairs[i] = p;
    }
}

__device__ __forceinline__ __half2 h2bits(uint32_t u) {
    return *reinterpret_cast<__half2*>(&u);
}

// sigmoid(x) = 0.5 + 0.5*tanh(x/2)  -- single MUFU.TANH
__device__ __forceinline__ float sigmoid_fast(float x) {
    float t;
    asm("tanh.approx.f32 %0, %1;" : "=f"(t) : "f"(x * 0.5f));
    return fmaf(t, 0.5f, 0.5f);
}
// accurate-ish sigmoid for the output layer
__device__ __forceinline__ float sigmoid_ref(float x) {
    return __fdividef(1.f, 1.f + __expf(-x));
}

// --------------------------- one layer ------------------------------------
template <bool LAST>
__device__ __forceinline__ void do_layer(char* sm, int l, int warp, int lane,
                                         const float* __restrict__ biases,
                                         int row0, bool active) {
    const int width = NIN + l * WIDTH;
    const int w0    = warp * UNITS_PER_WARP;     // 16 warps x 16 units = 256
    const Pair*  pt = g_pairs + (size_t)(l * WIDTH + w0) * KK;
    const float* bl = biases + l * WIDTH + w0;
    const int    lb = lane * 4;                  // byte offset of this lane's row pair

    // prefetch unit 0's 16 pairs (8 x uint4, uniform address -> 1 sector each)
    const uint4* p = reinterpret_cast<const uint4*>(pt);
    uint4 q0 = __ldg(p + 0), q1 = __ldg(p + 1), q2 = __ldg(p + 2), q3 = __ldg(p + 3);
    uint4 q4 = __ldg(p + 4), q5 = __ldg(p + 5), q6 = __ldg(p + 6), q7 = __ldg(p + 7);

#pragma unroll 1
    for (int u = 0; u < UNITS_PER_WARP; ++u) {
        uint4 n0, n1, n2, n3, n4, n5, n6, n7;
        if (u < UNITS_PER_WARP - 1) {   // software prefetch next unit's pairs
            const uint4* pn = reinterpret_cast<const uint4*>(pt + (u + 1) * KK);
            n0 = __ldg(pn + 0); n1 = __ldg(pn + 1); n2 = __ldg(pn + 2); n3 = __ldg(pn + 3);
            n4 = __ldg(pn + 4); n5 = __ldg(pn + 5); n6 = __ldg(pn + 6); n7 = __ldg(pn + 7);
        } else {
            n0 = q0; n1 = q1; n2 = q2; n3 = q3; n4 = q4; n5 = q5; n6 = q6; n7 = q7;
        }

        __half2 a0 = __float2half2_rn(0.f), a1 = a0, a2 = a0, a3 = a0;
        // 16 gathers, round-robin over 4 fp16 accumulators (<=4 terms each)
        a0 = __hfma2(*(const __half2*)(sm + q0.x + lb), h2bits(q0.y), a0);
        a1 = __hfma2(*(const __half2*)(sm + q0.z + lb), h2bits(q0.w), a1);
        a2 = __hfma2(*(const __half2*)(sm + q1.x + lb), h2bits(q1.y), a2);
        a3 = __hfma2(*(const __half2*)(sm + q1.z + lb), h2bits(q1.w), a3);
        a0 = __hfma2(*(const __half2*)(sm + q2.x + lb), h2bits(q2.y), a0);
        a1 = __hfma2(*(const __half2*)(sm + q2.z + lb), h2bits(q2.w), a1);
        a2 = __hfma2(*(const __half2*)(sm + q3.x + lb), h2bits(q3.y), a2);
        a3 = __hfma2(*(const __half2*)(sm + q3.z + lb), h2bits(q3.w), a3);
        a0 = __hfma2(*(const __half2*)(sm + q4.x + lb), h2bits(q4.y), a0);
        a1 = __hfma2(*(const __half2*)(sm + q4.z + lb), h2bits(q4.w), a1);
        a2 = __hfma2(*(const __half2*)(sm + q5.x + lb), h2bits(q5.y), a2);
        a3 = __hfma2(*(const __half2*)(sm + q5.z + lb), h2bits(q5.w), a3);
        a0 = __hfma2(*(const __half2*)(sm + q6.x + lb), h2bits(q6.y), a0);
        a1 = __hfma2(*(const __half2*)(sm + q6.z + lb), h2bits(q6.w), a1);
        a2 = __hfma2(*(const __half2*)(sm + q7.x + lb), h2bits(q7.y), a2);
        a3 = __hfma2(*(const __half2*)(sm + q7.z + lb), h2bits(q7.w), a3);

        // combine in fp32, add bias, sigmoid
        float2 f0 = __half22float2(a0), f1 = __half22float2(a1);
        float2 f2 = __half22float2(a2), f3 = __half22float2(a3);
        float  b  = __ldg(bl + u);
        float  sx = ((f0.x + f1.x) + (f2.x + f3.x)) + b;   // row 2*lane
        float  sy = ((f0.y + f1.y) + (f2.y + f3.y)) + b;   // row 2*lane+1
        float  s0, s1;
        if (!LAST) { s0 = sigmoid_fast(sx); s1 = sigmoid_fast(sy); }
        else       { s0 = sigmoid_ref(sx);  s1 = sigmoid_ref(sy);  }

        if (active) {
            if (!LAST) {
                *(__half2*)(sm + (width + w0 + u) * ROW_BYTES + lb) =
                    __floats2half2_rn(s0, s1);
            } else {
                int r = row0 + 2 * lane;
                if (r < BB) {   // B even, rows pair-aligned -> one guard suffices
                    *reinterpret_cast<float2*>(&g_out_t[(size_t)(w0 + u) * BB + r]) =
                        make_float2(s0, s1);
                }
            }
        }

        q0 = n0; q1 = n1; q2 = n2; q3 = n3; q4 = n4; q5 = n5; q6 = n6; q7 = n7;
    }
}

// --------------------------- main kernel -----------------------------------
__global__ void __launch_bounds__(NTHREADS, 1)
ffn_main(const float* __restrict__ inp, const float* __restrict__ biases) {
    extern __shared__ char sm[];
    const int tid  = threadIdx.x;
    const int lane = tid & 31;
    const int warp = tid >> 5;
    const int row0 = blockIdx.x * RROWS;

    // stage input tile [60 rows x 128 feats] transposed into smem as fp16
    for (int idx = tid; idx < RROWS * NIN; idx += NTHREADS) {
        int r = idx >> 7;          // 0..59
        int c = idx & 127;         // coalesced gmem read over c
        float v = 0.f;
        int gr = row0 + r;
        if (gr < BB) v = inp[gr * NIN + c];
        *reinterpret_cast<__half*>(sm + c * ROW_BYTES + r * 2) = __float2half_rn(v);
    }
    __syncthreads();

    const bool active = lane < (RROWS / 2);   // 30 row-pairs per warp

#pragma unroll 1
    for (int l = 0; l < NLAYER - 1; ++l) {
        do_layer<false>(sm, l, warp, lane, biases, row0, active);
        __syncthreads();   // layer-l outputs visible before layer-(l+1) gathers
    }
    do_layer<true>(sm, NLAYER - 1, warp, lane, biases, row0, active);
}

// --------------------------- output transpose ------------------------------
__global__ void transpose_kernel(float* __restrict__ out) {
    __shared__ float t[32][33];
    int rb = blockIdx.x * 32;    // row tile
    int cb = blockIdx.y * 32;    // feature tile
    int x = threadIdx.x, y = threadIdx.y;   // 32 x 8
#pragma unroll
    for (int i = 0; i < 32; i += 8)
        t[y + i][x] = g_out_t[(size_t)(cb + y + i) * BB + rb + x];
    __syncthreads();
#pragma unroll
    for (int i = 0; i < 32; i += 8)
        out[(size_t)(rb + y + i) * WIDTH + cb + x] = t[x][y + i];
}

// --------------------------- launcher --------------------------------------
extern "C" void kernel_launch(void* const* d_in, const int* in_sizes, int n_in,
                              void* d_out, int out_size) {
    const float* inp     = (const float*)d_in[0];   // (32768, 128) f32
    const float* weights = (const float*)d_in[1];   // (8, 256, 16) f32
    const float* biases  = (const float*)d_in[2];   // (8, 256)     f32
    const int*   edge    = (const int*)  d_in[3];   // (8, 256, 16) i32
    float* out = (float*)d_out;                     // (32768, 256) f32

    cudaFuncSetAttribute(ffn_main, cudaFuncAttributeMaxDynamicSharedMemorySize,
                         SMEM_BYTES);

    prepack_kernel<<<(NPAIR + 255) / 256, 256>>>(weights, edge);
    ffn_main<<<(BB + RROWS - 1) / RROWS, NTHREADS, SMEM_BYTES>>>(inp, biases);
    transpose_kernel<<<dim3(BB / 32, WIDTH / 32), dim3(32, 8)>>>(out);
}

// round 7
// speedup vs baseline: 1.2248x; 1.0355x over previous
#include <cuda_runtime.h>
#include <cuda_fp16.h>
#include <stdint.h>

// ---------------------------------------------------------------------------
// Sparse gather-MLP (B=32768, 8 layers, W=256, K=16 random gathers/unit).
//
// Per-block batch tile of R=60 rows entirely in shared memory, feature-major
// fp16 [feat][60 rows]. Gather index is uniform across the warp ->
// conflict-free broadcast-indexed LDS.32 of half2 (2 rows/lane, lanes 0..29).
// Pair table {byte_off, half2(w)} prepacked in gmem, uniform LDG.128.
//
// R6: 1024 threads (32 warps, 8/SMSP) for latency hiding, 8 units/warp;
// dropped software prefetch (register headroom at 64-reg cap); full-fp16
// tail on hidden layers (HADD2 combine + prepacked half2 bias +
// tanh.approx.f16x2 sigmoid). fp32 exp-sigmoid kept on the output layer.
// ---------------------------------------------------------------------------

#define NLAYER 8
#define WIDTH  256
#define KK     16
#define NIN    128
#define BB     32768
#define RROWS  60
#define ROW_BYTES (RROWS * 2)                       // 120 bytes per feature row
#define TOTAL_FEAT (NIN + (NLAYER - 1) * WIDTH)     // 1920 stored features
#define SMEM_BYTES (TOTAL_FEAT * ROW_BYTES + 256)   // + pad for lane 30/31 overread
#define NPAIR (NLAYER * WIDTH * KK)
#define NTHREADS 1024
#define UNITS_PER_WARP (WIDTH / (NTHREADS / 32))    // 8

struct Pair { uint32_t off; uint32_t w2; };         // byte offset, half2 weight

__device__ Pair    g_pairs[NPAIR];                  // 256 KB prepacked table
__device__ __half2 g_bias2[NLAYER * WIDTH];         // bias as half2 (broadcast)
__device__ float   g_out_t[(size_t)WIDTH * BB];     // transposed output scratch

// --------------------------- prepack -------------------------------------
__global__ void prepack_kernel(const float* __restrict__ w,
                               const int* __restrict__ e,
                               const float* __restrict__ b) {
    int i = blockIdx.x * blockDim.x + threadIdx.x;
    if (i < NPAIR) {
        __half2 h = __float2half2_rn(w[i]);
        Pair p;
        p.off = (uint32_t)e[i] * (uint32_t)ROW_BYTES;
        p.w2  = *reinterpret_cast<uint32_t*>(&h);
        g_pairs[i] = p;
    }
    if (i < NLAYER * WIDTH) g_bias2[i] = __float2half2_rn(b[i]);
}

__device__ __forceinline__ __half2 h2bits(uint32_t u) {
    return *reinterpret_cast<__half2*>(&u);
}

__device__ __forceinline__ __half2 h2_tanh(__half2 x) {
    uint32_t xi = *reinterpret_cast<uint32_t*>(&x), yo;
    asm("tanh.approx.f16x2 %0, %1;" : "=r"(yo) : "r"(xi));
    return *reinterpret_cast<__half2*>(&yo);
}

__device__ __forceinline__ float sigmoid_ref(float x) {
    return __fdividef(1.f, 1.f + __expf(-x));
}

// --------------------------- one layer ------------------------------------
template <bool LAST>
__device__ __forceinline__ void do_layer(char* sm, char* smlb, int l, int warp,
                                         int lane, int row0, bool active) {
    const int width = NIN + l * WIDTH;
    const int w0    = warp * UNITS_PER_WARP;     // 32 warps x 8 units = 256
    const Pair*    pt = g_pairs + (size_t)(l * WIDTH + w0) * KK;
    const __half2* bl = g_bias2 + l * WIDTH + w0;
    const int      lb = lane * 4;

    const __half2 h05 = __float2half2_rn(0.5f);

#pragma unroll 1
    for (int u = 0; u < UNITS_PER_WARP; ++u) {
        const uint4* p = reinterpret_cast<const uint4*>(pt + u * KK);
        __half2 a0 = __float2half2_rn(0.f), a1 = a0, a2 = a0, a3 = a0;
        {   // first 8 gathers (4 x uint4 pairs, uniform -> 1 sector each)
            uint4 q0 = __ldg(p + 0), q1 = __ldg(p + 1);
            uint4 q2 = __ldg(p + 2), q3 = __ldg(p + 3);
            a0 = __hfma2(*(const __half2*)(smlb + q0.x), h2bits(q0.y), a0);
            a1 = __hfma2(*(const __half2*)(smlb + q0.z), h2bits(q0.w), a1);
            a2 = __hfma2(*(const __half2*)(smlb + q1.x), h2bits(q1.y), a2);
            a3 = __hfma2(*(const __half2*)(smlb + q1.z), h2bits(q1.w), a3);
            a0 = __hfma2(*(const __half2*)(smlb + q2.x), h2bits(q2.y), a0);
            a1 = __hfma2(*(const __half2*)(smlb + q2.z), h2bits(q2.w), a1);
            a2 = __hfma2(*(const __half2*)(smlb + q3.x), h2bits(q3.y), a2);
            a3 = __hfma2(*(const __half2*)(smlb + q3.z), h2bits(q3.w), a3);
        }
        {   // second 8 gathers
            uint4 q4 = __ldg(p + 4), q5 = __ldg(p + 5);
            uint4 q6 = __ldg(p + 6), q7 = __ldg(p + 7);
            a0 = __hfma2(*(const __half2*)(smlb + q4.x), h2bits(q4.y), a0);
            a1 = __hfma2(*(const __half2*)(smlb + q4.z), h2bits(q4.w), a1);
            a2 = __hfma2(*(const __half2*)(smlb + q5.x), h2bits(q5.y), a2);
            a3 = __hfma2(*(const __half2*)(smlb + q5.z), h2bits(q5.w), a3);
            a0 = __hfma2(*(const __half2*)(smlb + q6.x), h2bits(q6.y), a0);
            a1 = __hfma2(*(const __half2*)(smlb + q6.z), h2bits(q6.w), a1);
            a2 = __hfma2(*(const __half2*)(smlb + q7.x), h2bits(q7.y), a2);
            a3 = __hfma2(*(const __half2*)(smlb + q7.z), h2bits(q7.w), a3);
        }

        // combine + bias in fp16
        __half2 s = __hadd2(__hadd2(a0, a1), __hadd2(a2, a3));
        s = __hadd2(s, __ldg((const __half2*)bl + u));

        if (!LAST) {
            // sigmoid(x) = 0.5 + 0.5*tanh(x/2), all fp16x2
            __half2 t = h2_tanh(__hmul2(s, h05));
            __half2 o = __hfma2(t, h05, h05);
            if (active)
                *(__half2*)(sm + (width + w0 + u) * ROW_BYTES + lb) = o;
        } else {
            float2 f = __half22float2(s);
            float s0 = sigmoid_ref(f.x), s1 = sigmoid_ref(f.y);
            if (active) {
                int r = row0 + 2 * lane;
                if (r < BB) {
                    *reinterpret_cast<float2*>(&g_out_t[(size_t)(w0 + u) * BB + r]) =
                        make_float2(s0, s1);
                }
            }
        }
    }
}

// --------------------------- main kernel -----------------------------------
__global__ void __launch_bounds__(NTHREADS, 1)
ffn_main(const float* __restrict__ inp) {
    extern __shared__ char sm[];
    const int tid  = threadIdx.x;
    const int lane = tid & 31;
    const int warp = tid >> 5;
    const int row0 = blockIdx.x * RROWS;

    // stage input tile [60 rows x 128 feats] transposed into smem as fp16
    for (int idx = tid; idx < RROWS * NIN; idx += NTHREADS) {
        int r = idx >> 7;          // 0..59
        int c = idx & 127;         // coalesced gmem read over c
        float v = 0.f;
        int gr = row0 + r;
        if (gr < BB) v = inp[gr * NIN + c];
        *reinterpret_cast<__half*>(sm + c * ROW_BYTES + r * 2) = __float2half_rn(v);
    }
    __syncthreads();

    char* smlb = sm + lane * 4;                // per-lane gather base
    const bool active = lane < (RROWS / 2);    // 30 row-pairs per warp

#pragma unroll 1
    for (int l = 0; l < NLAYER - 1; ++l) {
        do_layer<false>(sm, smlb, l, warp, lane, row0, active);
        __syncthreads();   // layer-l outputs visible before layer-(l+1) gathers
    }
    do_layer<true>(sm, smlb, NLAYER - 1, warp, lane, row0, active);
}

// --------------------------- output transpose ------------------------------
__global__ void transpose_kernel(float* __restrict__ out) {
    __shared__ float t[32][33];
    int rb = blockIdx.x * 32;    // row tile
    int cb = blockIdx.y * 32;    // feature tile
    int x = threadIdx.x, y = threadIdx.y;   // 32 x 8
#pragma unroll
    for (int i = 0; i < 32; i += 8)
        t[y + i][x] = g_out_t[(size_t)(cb + y + i) * BB + rb + x];
    __syncthreads();
#pragma unroll
    for (int i = 0; i < 32; i += 8)
        out[(size_t)(rb + y + i) * WIDTH + cb + x] = t[x][y + i];
}

// --------------------------- launcher --------------------------------------
extern "C" void kernel_launch(void* const* d_in, const int* in_sizes, int n_in,
                              void* d_out, int out_size) {
    const float* inp     = (const float*)d_in[0];   // (32768, 128) f32
    const float* weights = (const float*)d_in[1];   // (8, 256, 16) f32
    const float* biases  = (const float*)d_in[2];   // (8, 256)     f32
    const int*   edge    = (const int*)  d_in[3];   // (8, 256, 16) i32
    float* out = (float*)d_out;                     // (32768, 256) f32

    cudaFuncSetAttribute(ffn_main, cudaFuncAttributeMaxDynamicSharedMemorySize,
                         SMEM_BYTES);

    prepack_kernel<<<(NPAIR + 255) / 256, 256>>>(weights, edge, biases);
    ffn_main<<<(BB + RROWS - 1) / RROWS, NTHREADS, SMEM_BYTES>>>(inp);
    transpose_kernel<<<dim3(BB / 32, WIDTH / 32), dim3(32, 8)>>>(out);
}